// round 10
// baseline (speedup 1.0000x reference)
#include <cuda_runtime.h>

#define BB 8
#define LL 512
#define KK 512
#define MM 64
#define NN 64
#define PDIM 64
#define DD 64

// scratch (device globals; no allocations)
__device__ float g_ssT [BB * KK * LL];        // 8 MB  exp(scores) stored [b][k][l]
__device__ float g_sum4[BB * 4 * LL];         // 64 KB per-(b,ktile) partial row sums
__device__ float g_vkc [BB * KK * NN];        // 1 MB
__device__ float g_tmp4[BB * 4 * LL * NN];    // 4 MB  split-K partial tmp

#define KB_STRIDE 68
#define QT_STRIDE 68

// ============ K1: vkc[b,k,n] = sum_p vk[b,k,p,n] * vexp[b,k,p] ============
// 4 bk-slabs per block, float4 loads, vexp staged in smem. (measured 14.1us)
__global__ void __launch_bounds__(256) kv_kernel(
    const float* __restrict__ vk, const float* __restrict__ vexp) {
    __shared__ float sve[256];
    __shared__ __align__(16) float4 red[256];
    int t = threadIdx.x;
    int bk0 = blockIdx.x * 4;

    sve[t] = vexp[(size_t)bk0 * PDIM + t];
    __syncthreads();

    int slab = t >> 6;
    int tt = t & 63;
    int n4 = tt & 15;
    int pg = tt >> 4;
    const float4* vk4 = (const float4*)(vk + (size_t)(bk0 + slab) * PDIM * NN);
    const float* ve = &sve[slab * 64];
    float4 acc = make_float4(0.f, 0.f, 0.f, 0.f);
#pragma unroll
    for (int i = 0; i < 16; i++) {
        int p = pg * 16 + i;
        float4 a = vk4[p * 16 + n4];
        float e = ve[p];
        acc.x += a.x * e; acc.y += a.y * e; acc.z += a.z * e; acc.w += a.w * e;
    }
    red[t] = acc;
    __syncthreads();
    if (tt < 16) {
        float4 r0 = red[slab * 64 + n4];
        float4 r1 = red[slab * 64 + 16 + n4];
        float4 r2 = red[slab * 64 + 32 + n4];
        float4 r3 = red[slab * 64 + 48 + n4];
        float4 o = make_float4(r0.x + r1.x + r2.x + r3.x, r0.y + r1.y + r2.y + r3.y,
                               r0.z + r1.z + r2.z + r3.z, r0.w + r1.w + r2.w + r3.w);
        *(float4*)&g_vkc[(size_t)(bk0 + slab) * NN + n4 * 4] = o;
    }
}

// ============ K2: scores^T + exp + partial row sums (standalone) ============
// block = (b, 64 l-rows, 128 k-cols); thread tile 4k x 8l; 51.5KB smem -> 2 CTA/SM
__global__ void __launch_bounds__(256) sc_kernel(
    const float* __restrict__ q, const float* __restrict__ k,
    const float* __restrict__ scale_p) {
    extern __shared__ float s[];
    float* kbuf = s;                        // [128][KB_STRIDE]
    float* qT   = s + 128 * KB_STRIDE;      // [64][QT_STRIDE]
    float* ssum = qT + 64 * QT_STRIDE;      // [64]
    int t = threadIdx.x;
    int bid = blockIdx.x;
    int b  = bid >> 5;
    int r  = bid & 31;
    int l0 = (r >> 2) * 64;
    int kt = r & 3;
    int k0 = kt * 128;

    // load k tile [128][64] coalesced
#pragma unroll
    for (int j = 0; j < 8; j++) {
        int v = t + j * 256;
        int row = v >> 4, c4 = v & 15;
        float4 x = *(const float4*)&k[((size_t)(b * KK + k0 + row)) * DD + c4 * 4];
        *(float4*)&kbuf[row * KB_STRIDE + c4 * 4] = x;
    }
    // transpose q tile 64x64 -> qT[d][l]
#pragma unroll
    for (int i = 0; i < 4; i++) {
        int l = (t >> 4) + 16 * i;
        int d4 = t & 15;
        float4 x = *(const float4*)&q[((size_t)(b * LL + l0 + l)) * DD + d4 * 4];
        qT[(d4 * 4 + 0) * QT_STRIDE + l] = x.x;
        qT[(d4 * 4 + 1) * QT_STRIDE + l] = x.y;
        qT[(d4 * 4 + 2) * QT_STRIDE + l] = x.z;
        qT[(d4 * 4 + 3) * QT_STRIDE + l] = x.w;
    }
    if (t < 64) ssum[t] = 0.f;
    __syncthreads();

    int tkg = t >> 3;          // k rows tkg*4..+3
    int tlg = t & 7;           // l groups (tlg*4 and 32+tlg*4)
    float acc[4][8];
#pragma unroll
    for (int a = 0; a < 4; a++)
#pragma unroll
        for (int c = 0; c < 8; c++) acc[a][c] = 0.f;

#pragma unroll 2
    for (int d0 = 0; d0 < DD; d0 += 4) {
        float4 kv[4];
#pragma unroll
        for (int ki = 0; ki < 4; ki++)
            kv[ki] = *(float4*)&kbuf[(tkg * 4 + ki) * KB_STRIDE + d0];
#pragma unroll
        for (int dd = 0; dd < 4; dd++) {
            float4 qa = *(float4*)&qT[(d0 + dd) * QT_STRIDE + tlg * 4];
            float4 qb = *(float4*)&qT[(d0 + dd) * QT_STRIDE + 32 + tlg * 4];
            float kd[4];
            kd[0] = ((float*)&kv[0])[dd];
            kd[1] = ((float*)&kv[1])[dd];
            kd[2] = ((float*)&kv[2])[dd];
            kd[3] = ((float*)&kv[3])[dd];
#pragma unroll
            for (int ki = 0; ki < 4; ki++) {
                acc[ki][0] += kd[ki] * qa.x;
                acc[ki][1] += kd[ki] * qa.y;
                acc[ki][2] += kd[ki] * qa.z;
                acc[ki][3] += kd[ki] * qa.w;
                acc[ki][4] += kd[ki] * qb.x;
                acc[ki][5] += kd[ki] * qb.y;
                acc[ki][6] += kd[ki] * qb.z;
                acc[ki][7] += kd[ki] * qb.w;
            }
        }
    }

    float scale = *scale_p;
    float sacc[8];
#pragma unroll
    for (int j = 0; j < 8; j++) sacc[j] = 0.f;
#pragma unroll
    for (int ki = 0; ki < 4; ki++) {
        float4 e0, e1;
        e0.x = __expf(acc[ki][0] * scale);
        e0.y = __expf(acc[ki][1] * scale);
        e0.z = __expf(acc[ki][2] * scale);
        e0.w = __expf(acc[ki][3] * scale);
        e1.x = __expf(acc[ki][4] * scale);
        e1.y = __expf(acc[ki][5] * scale);
        e1.z = __expf(acc[ki][6] * scale);
        e1.w = __expf(acc[ki][7] * scale);
        sacc[0] += e0.x; sacc[1] += e0.y; sacc[2] += e0.z; sacc[3] += e0.w;
        sacc[4] += e1.x; sacc[5] += e1.y; sacc[6] += e1.z; sacc[7] += e1.w;
        size_t base = ((size_t)(b * KK + k0 + tkg * 4 + ki)) * LL + l0;
        *(float4*)&g_ssT[base + tlg * 4]      = e0;
        *(float4*)&g_ssT[base + 32 + tlg * 4] = e1;
    }
#pragma unroll
    for (int j = 0; j < 4; j++) atomicAdd(&ssum[tlg * 4 + j], sacc[j]);
#pragma unroll
    for (int j = 0; j < 4; j++) atomicAdd(&ssum[32 + tlg * 4 + j], sacc[4 + j]);
    __syncthreads();
    if (t < 64) g_sum4[((size_t)(b * 4 + kt)) * LL + l0 + t] = ssum[t];
}

// ============ K3: tmp4 = E^T(chunk) outer-product vkc(chunk), split-K ============
#define ES 68
#define VS 68
__global__ void __launch_bounds__(256) k2_kernel() {
    extern __shared__ float s[];
    float* Es = s;                 // [128][ES]  E^T chunk: [k][l]
    float* Vs = s + 128 * ES;      // [128][VS]  vkc chunk: [k][n]
    int t = threadIdx.x;
    int bid = blockIdx.x;
    int b  = bid >> 5;
    int r  = bid & 31;
    int l0 = (r >> 2) * 64;
    int ks = r & 3;
    int k0 = ks * 128;

#pragma unroll
    for (int j = 0; j < 8; j++) {
        int v = t + j * 256;
        int row = v >> 4, c4 = v & 15;
        float4 x = *(const float4*)&g_ssT[((size_t)(b * KK + k0 + row)) * LL + l0 + c4 * 4];
        *(float4*)&Es[row * ES + c4 * 4] = x;
    }
#pragma unroll
    for (int j = 0; j < 8; j++) {
        int v = t + j * 256;
        int row = v >> 4, c4 = v & 15;
        float4 x = *(const float4*)&g_vkc[((size_t)(b * KK + k0 + row)) * NN + c4 * 4];
        *(float4*)&Vs[row * VS + c4 * 4] = x;
    }
    __syncthreads();

    int tn = t >> 4, tl = t & 15;   // 4l x 4n per thread
    float acc[4][4];
#pragma unroll
    for (int a = 0; a < 4; a++)
#pragma unroll
        for (int c = 0; c < 4; c++) acc[a][c] = 0.f;
#pragma unroll 4
    for (int kk = 0; kk < 128; kk++) {
        float4 e4 = *(float4*)&Es[kk * ES + tl * 4];
        float4 v4 = *(float4*)&Vs[kk * VS + tn * 4];
        float ee[4] = {e4.x, e4.y, e4.z, e4.w};
        float vv[4] = {v4.x, v4.y, v4.z, v4.w};
#pragma unroll
        for (int li = 0; li < 4; li++)
#pragma unroll
            for (int nj = 0; nj < 4; nj++)
                acc[li][nj] += ee[li] * vv[nj];
    }
#pragma unroll
    for (int li = 0; li < 4; li++) {
        int l = l0 + tl * 4 + li;
        float4 o = {acc[li][0], acc[li][1], acc[li][2], acc[li][3]};
        *(float4*)&g_tmp4[(((size_t)(b * 4 + ks)) * LL + l) * NN + tn * 4] = o;
    }
}

// ============ K4: attn = vq @ tmp (combined+normalized), residual + LN ============
__global__ void __launch_bounds__(256) k3_kernel(
    const float* __restrict__ q, const float* __restrict__ vq,
    const float* __restrict__ gamma, const float* __restrict__ beta,
    float* __restrict__ out) {
    int bl = blockIdx.x;             // b*512 + l
    int b = bl >> 9, l = bl & 511;
    __shared__ __align__(16) float stmp[64];
    __shared__ float sq[64];
    __shared__ float so[64];
    __shared__ float rs[8], rq[8];
    int t = threadIdx.x;
    if (t < 64) {
        float ssum = 0.f;
        float v = 0.f;
#pragma unroll
        for (int i = 0; i < 4; i++) {
            ssum += g_sum4[((size_t)(b * 4 + i)) * LL + l];
            v    += g_tmp4[(((size_t)(b * 4 + i)) * LL + l) * NN + t];
        }
        stmp[t] = v / ssum;
        sq[t]   = q[(size_t)bl * DD + t];
    }
    __syncthreads();

    int n4 = t & 15;
    float4 tm = ((float4*)stmp)[n4];
    const float4* vq4 = (const float4*)(vq + (size_t)bl * MM * NN);
    float p[4];
#pragma unroll
    for (int i = 0; i < 4; i++) {
        float4 v = vq4[t + i * 256];         // m = (t>>4) + 16*i, n-chunk = n4
        p[i] = v.x * tm.x + v.y * tm.y + v.z * tm.z + v.w * tm.w;
    }
#pragma unroll
    for (int o = 8; o; o >>= 1)
#pragma unroll
        for (int i = 0; i < 4; i++)
            p[i] += __shfl_down_sync(0xFFFFFFFFu, p[i], o, 16);
    if ((t & 15) == 0) {
        int g = t >> 4;
#pragma unroll
        for (int i = 0; i < 4; i++) so[g + 16 * i] = p[i];
    }
    __syncthreads();

    int m = t & 63;
    float x = sq[m] + so[m];                 // residual (M == D)
    float s1 = x, s2 = x * x;
#pragma unroll
    for (int o = 16; o; o >>= 1) {
        s1 += __shfl_xor_sync(0xFFFFFFFFu, s1, o);
        s2 += __shfl_xor_sync(0xFFFFFFFFu, s2, o);
    }
    int lane = t & 31, w = t >> 5;
    if (lane == 0) { rs[w] = s1; rq[w] = s2; }
    __syncthreads();
    float a = 0.f, b2 = 0.f;
#pragma unroll
    for (int i = 0; i < 8; i++) { a += rs[i]; b2 += rq[i]; }
    float mu   = a * (1.f / 256.f);          // each m replicated 4x -> exact mean
    float var  = b2 * (1.f / 256.f) - mu * mu;
    float rstd = rsqrtf(var + 1e-3f);
    if (t < 64)
        out[(size_t)bl * MM + m] = (x - mu) * rstd * gamma[m] + beta[m];
}

extern "C" void kernel_launch(void* const* d_in, const int* in_sizes, int n_in,
                              void* d_out, int out_size) {
    const float* q     = (const float*)d_in[0];
    const float* k     = (const float*)d_in[1];
    const float* vq    = (const float*)d_in[2];
    const float* vk    = (const float*)d_in[3];
    const float* vexp  = (const float*)d_in[4];
    const float* scale = (const float*)d_in[5];
    const float* gamma = (const float*)d_in[6];
    const float* beta  = (const float*)d_in[7];
    float* out = (float*)d_out;

    kv_kernel<<<BB * KK / 4, 256>>>(vk, vexp);

    int smemS = (128 * KB_STRIDE + 64 * QT_STRIDE + 64) * (int)sizeof(float);
    cudaFuncSetAttribute(sc_kernel, cudaFuncAttributeMaxDynamicSharedMemorySize, smemS);
    sc_kernel<<<256, 256, smemS>>>(q, k, scale);

    int smem2 = (128 * ES + 128 * VS) * (int)sizeof(float);
    cudaFuncSetAttribute(k2_kernel, cudaFuncAttributeMaxDynamicSharedMemorySize, smem2);
    k2_kernel<<<256, 256, smem2>>>();

    k3_kernel<<<BB * LL, 256>>>(q, vq, gamma, beta, out);
}

// round 11
// speedup vs baseline: 1.0046x; 1.0046x over previous
#include <cuda_runtime.h>

#define BB 8
#define LL 512
#define KK 512
#define MM 64
#define NN 64
#define PDIM 64
#define DD 64

// scratch (device globals; no allocations)
__device__ float g_ssT [BB * KK * LL];        // 8 MB  exp(scores) stored [b][k][l]
__device__ float g_sum4[BB * 4 * LL];         // 64 KB per-(b,ktile) partial row sums
__device__ float g_vkc [BB * KK * NN];        // 1 MB
__device__ float g_tmp4[BB * 4 * LL * NN];    // 4 MB  split-K partial tmp

#define KB_STRIDE 68
#define QT_STRIDE 68

// ============ P1: interleaved [vkc stream | scores^T+exp+sums] ============
// grid 1280: each group of 5 blocks = 4 kv-blocks + 1 sc-block (uniform SM mix)
__global__ void __launch_bounds__(256) p1_kernel(
    const float* __restrict__ q, const float* __restrict__ k,
    const float* __restrict__ vk, const float* __restrict__ vexp,
    const float* __restrict__ scale_p) {
    extern __shared__ float s[];
    int t = threadIdx.x;
    int bid = blockIdx.x;
    int g = bid / 5;
    int r5 = bid - g * 5;

    if (r5 == 4) {
        // ---- sc block g (0..255): (b, 64 l-rows, 128 k-cols) ----
        float* kbuf = s;                        // [128][KB_STRIDE]
        float* qT   = s + 128 * KB_STRIDE;      // [64][QT_STRIDE]
        float* ssum = qT + 64 * QT_STRIDE;      // [64]
        int b  = g >> 5;
        int r  = g & 31;
        int l0 = (r >> 2) * 64;
        int kt = r & 3;
        int k0 = kt * 128;

#pragma unroll
        for (int j = 0; j < 8; j++) {
            int v = t + j * 256;
            int row = v >> 4, c4 = v & 15;
            float4 x = *(const float4*)&k[((size_t)(b * KK + k0 + row)) * DD + c4 * 4];
            *(float4*)&kbuf[row * KB_STRIDE + c4 * 4] = x;
        }
#pragma unroll
        for (int i = 0; i < 4; i++) {
            int l = (t >> 4) + 16 * i;
            int d4 = t & 15;
            float4 x = *(const float4*)&q[((size_t)(b * LL + l0 + l)) * DD + d4 * 4];
            qT[(d4 * 4 + 0) * QT_STRIDE + l] = x.x;
            qT[(d4 * 4 + 1) * QT_STRIDE + l] = x.y;
            qT[(d4 * 4 + 2) * QT_STRIDE + l] = x.z;
            qT[(d4 * 4 + 3) * QT_STRIDE + l] = x.w;
        }
        if (t < 64) ssum[t] = 0.f;
        __syncthreads();

        int tkg = t >> 3;          // k rows tkg*4..+3
        int tlg = t & 7;           // l groups (tlg*4 and 32+tlg*4)
        float acc[4][8];
#pragma unroll
        for (int a = 0; a < 4; a++)
#pragma unroll
            for (int c = 0; c < 8; c++) acc[a][c] = 0.f;

#pragma unroll 2
        for (int d0 = 0; d0 < DD; d0 += 4) {
            float4 kv4[4];
#pragma unroll
            for (int ki = 0; ki < 4; ki++)
                kv4[ki] = *(float4*)&kbuf[(tkg * 4 + ki) * KB_STRIDE + d0];
#pragma unroll
            for (int dd = 0; dd < 4; dd++) {
                float4 qa = *(float4*)&qT[(d0 + dd) * QT_STRIDE + tlg * 4];
                float4 qb = *(float4*)&qT[(d0 + dd) * QT_STRIDE + 32 + tlg * 4];
                float kd[4];
                kd[0] = ((float*)&kv4[0])[dd];
                kd[1] = ((float*)&kv4[1])[dd];
                kd[2] = ((float*)&kv4[2])[dd];
                kd[3] = ((float*)&kv4[3])[dd];
#pragma unroll
                for (int ki = 0; ki < 4; ki++) {
                    acc[ki][0] += kd[ki] * qa.x;
                    acc[ki][1] += kd[ki] * qa.y;
                    acc[ki][2] += kd[ki] * qa.z;
                    acc[ki][3] += kd[ki] * qa.w;
                    acc[ki][4] += kd[ki] * qb.x;
                    acc[ki][5] += kd[ki] * qb.y;
                    acc[ki][6] += kd[ki] * qb.z;
                    acc[ki][7] += kd[ki] * qb.w;
                }
            }
        }

        float scale = *scale_p;
        float sacc[8];
#pragma unroll
        for (int j = 0; j < 8; j++) sacc[j] = 0.f;
#pragma unroll
        for (int ki = 0; ki < 4; ki++) {
            float4 e0, e1;
            e0.x = __expf(acc[ki][0] * scale);
            e0.y = __expf(acc[ki][1] * scale);
            e0.z = __expf(acc[ki][2] * scale);
            e0.w = __expf(acc[ki][3] * scale);
            e1.x = __expf(acc[ki][4] * scale);
            e1.y = __expf(acc[ki][5] * scale);
            e1.z = __expf(acc[ki][6] * scale);
            e1.w = __expf(acc[ki][7] * scale);
            sacc[0] += e0.x; sacc[1] += e0.y; sacc[2] += e0.z; sacc[3] += e0.w;
            sacc[4] += e1.x; sacc[5] += e1.y; sacc[6] += e1.z; sacc[7] += e1.w;
            size_t base = ((size_t)(b * KK + k0 + tkg * 4 + ki)) * LL + l0;
            *(float4*)&g_ssT[base + tlg * 4]      = e0;
            *(float4*)&g_ssT[base + 32 + tlg * 4] = e1;
        }
#pragma unroll
        for (int j = 0; j < 4; j++) atomicAdd(&ssum[tlg * 4 + j], sacc[j]);
#pragma unroll
        for (int j = 0; j < 4; j++) atomicAdd(&ssum[32 + tlg * 4 + j], sacc[4 + j]);
        __syncthreads();
        if (t < 64) g_sum4[((size_t)(b * 4 + kt)) * LL + l0 + t] = ssum[t];
    } else {
        // ---- kv block (g*4 + r5): 4 bk slabs, float4 loads ----
        float* sve = s;                          // [256]
        float4* red = (float4*)(s + 256);        // [256]
        int bk0 = (g * 4 + r5) * 4;

        sve[t] = vexp[(size_t)bk0 * PDIM + t];
        __syncthreads();

        int slab = t >> 6;
        int tt = t & 63;
        int n4 = tt & 15;
        int pg = tt >> 4;
        const float4* vk4 = (const float4*)(vk + (size_t)(bk0 + slab) * PDIM * NN);
        const float* ve = &sve[slab * 64];
        float4 acc = make_float4(0.f, 0.f, 0.f, 0.f);
#pragma unroll
        for (int i = 0; i < 16; i++) {
            int p = pg * 16 + i;
            float4 a = vk4[p * 16 + n4];
            float e = ve[p];
            acc.x += a.x * e; acc.y += a.y * e; acc.z += a.z * e; acc.w += a.w * e;
        }
        red[t] = acc;
        __syncthreads();
        if (tt < 16) {
            float4 r0 = red[slab * 64 + n4];
            float4 r1 = red[slab * 64 + 16 + n4];
            float4 r2 = red[slab * 64 + 32 + n4];
            float4 r3 = red[slab * 64 + 48 + n4];
            float4 o = make_float4(r0.x + r1.x + r2.x + r3.x, r0.y + r1.y + r2.y + r3.y,
                                   r0.z + r1.z + r2.z + r3.z, r0.w + r1.w + r2.w + r3.w);
            *(float4*)&g_vkc[(size_t)(bk0 + slab) * NN + n4 * 4] = o;
        }
    }
}

// ============ K2: tmp4 = E^T(chunk) outer-product vkc(chunk), split-K ============
#define ES 68
#define VS 68
__global__ void __launch_bounds__(256) k2_kernel() {
    extern __shared__ float s[];
    float* Es = s;                 // [128][ES]  E^T chunk: [k][l]
    float* Vs = s + 128 * ES;      // [128][VS]  vkc chunk: [k][n]
    int t = threadIdx.x;
    int bid = blockIdx.x;
    int b  = bid >> 5;
    int r  = bid & 31;
    int l0 = (r >> 2) * 64;
    int ks = r & 3;
    int k0 = ks * 128;

#pragma unroll
    for (int j = 0; j < 8; j++) {
        int v = t + j * 256;
        int row = v >> 4, c4 = v & 15;
        float4 x = *(const float4*)&g_ssT[((size_t)(b * KK + k0 + row)) * LL + l0 + c4 * 4];
        *(float4*)&Es[row * ES + c4 * 4] = x;
    }
#pragma unroll
    for (int j = 0; j < 8; j++) {
        int v = t + j * 256;
        int row = v >> 4, c4 = v & 15;
        float4 x = *(const float4*)&g_vkc[((size_t)(b * KK + k0 + row)) * NN + c4 * 4];
        *(float4*)&Vs[row * VS + c4 * 4] = x;
    }
    __syncthreads();

    int tn = t >> 4, tl = t & 15;   // 4l x 4n per thread
    float acc[4][4];
#pragma unroll
    for (int a = 0; a < 4; a++)
#pragma unroll
        for (int c = 0; c < 4; c++) acc[a][c] = 0.f;
#pragma unroll 4
    for (int kk = 0; kk < 128; kk++) {
        float4 e4 = *(float4*)&Es[kk * ES + tl * 4];
        float4 v4 = *(float4*)&Vs[kk * VS + tn * 4];
        float ee[4] = {e4.x, e4.y, e4.z, e4.w};
        float vv[4] = {v4.x, v4.y, v4.z, v4.w};
#pragma unroll
        for (int li = 0; li < 4; li++)
#pragma unroll
            for (int nj = 0; nj < 4; nj++)
                acc[li][nj] += ee[li] * vv[nj];
    }
#pragma unroll
    for (int li = 0; li < 4; li++) {
        int l = l0 + tl * 4 + li;
        float4 o = {acc[li][0], acc[li][1], acc[li][2], acc[li][3]};
        *(float4*)&g_tmp4[(((size_t)(b * 4 + ks)) * LL + l) * NN + tn * 4] = o;
    }
}

// ============ K3: attn = vq @ tmp, residual + LN (2 rows/block, MLP 8) ============
__global__ void __launch_bounds__(256) k3_kernel(
    const float* __restrict__ q, const float* __restrict__ vq,
    const float* __restrict__ gamma, const float* __restrict__ beta,
    float* __restrict__ out) {
    int bl0 = blockIdx.x * 2;        // rows bl0, bl0+1
    int b = bl0 >> 9;
    __shared__ __align__(16) float stmp[2][64];
    __shared__ float sq[2][64];
    __shared__ float so[2][64];
    __shared__ float rs[2][8], rq[2][8];
    int t = threadIdx.x;
    if (t < 128) {
        int rr = t >> 6, tt = t & 63;
        int l = (bl0 & 511) + rr;
        float ssum = 0.f, v = 0.f;
#pragma unroll
        for (int i = 0; i < 4; i++) {
            ssum += g_sum4[((size_t)(b * 4 + i)) * LL + l];
            v    += g_tmp4[(((size_t)(b * 4 + i)) * LL + l) * NN + tt];
        }
        stmp[rr][tt] = v / ssum;
        sq[rr][tt]   = q[(size_t)(bl0 + rr) * DD + tt];
    }
    __syncthreads();

    int n4 = t & 15;
    const float4* vq0 = (const float4*)(vq + (size_t)bl0 * MM * NN);
    const float4* vq1 = vq0 + 1024;
    float4 va[4], vb[4];
#pragma unroll
    for (int i = 0; i < 4; i++) va[i] = vq0[t + i * 256];
#pragma unroll
    for (int i = 0; i < 4; i++) vb[i] = vq1[t + i * 256];

    float4 tm0 = ((float4*)stmp[0])[n4];
    float4 tm1 = ((float4*)stmp[1])[n4];
    float p0[4], p1[4];
#pragma unroll
    for (int i = 0; i < 4; i++) {
        p0[i] = va[i].x * tm0.x + va[i].y * tm0.y + va[i].z * tm0.z + va[i].w * tm0.w;
        p1[i] = vb[i].x * tm1.x + vb[i].y * tm1.y + vb[i].z * tm1.z + vb[i].w * tm1.w;
    }
#pragma unroll
    for (int o = 8; o; o >>= 1)
#pragma unroll
        for (int i = 0; i < 4; i++) {
            p0[i] += __shfl_down_sync(0xFFFFFFFFu, p0[i], o, 16);
            p1[i] += __shfl_down_sync(0xFFFFFFFFu, p1[i], o, 16);
        }
    if ((t & 15) == 0) {
        int gidx = t >> 4;
#pragma unroll
        for (int i = 0; i < 4; i++) {
            so[0][gidx + 16 * i] = p0[i];
            so[1][gidx + 16 * i] = p1[i];
        }
    }
    __syncthreads();

    int m = t & 63;
    int lane = t & 31, w = t >> 5;
    float x0 = sq[0][m] + so[0][m];          // residual (M == D)
    float x1 = sq[1][m] + so[1][m];
    float a0 = x0, q0 = x0 * x0, a1 = x1, q1 = x1 * x1;
#pragma unroll
    for (int o = 16; o; o >>= 1) {
        a0 += __shfl_xor_sync(0xFFFFFFFFu, a0, o);
        q0 += __shfl_xor_sync(0xFFFFFFFFu, q0, o);
        a1 += __shfl_xor_sync(0xFFFFFFFFu, a1, o);
        q1 += __shfl_xor_sync(0xFFFFFFFFu, q1, o);
    }
    if (lane == 0) { rs[0][w] = a0; rq[0][w] = q0; rs[1][w] = a1; rq[1][w] = q1; }
    __syncthreads();
    float sa0 = 0.f, sq0 = 0.f, sa1 = 0.f, sq1 = 0.f;
#pragma unroll
    for (int i = 0; i < 8; i++) {
        sa0 += rs[0][i]; sq0 += rq[0][i];
        sa1 += rs[1][i]; sq1 += rq[1][i];
    }
    if (t < 64) {
        float gm = gamma[m], bt = beta[m];
        float mu0   = sa0 * (1.f / 256.f);   // each m replicated 4x -> exact mean
        float var0  = sq0 * (1.f / 256.f) - mu0 * mu0;
        float mu1   = sa1 * (1.f / 256.f);
        float var1  = sq1 * (1.f / 256.f) - mu1 * mu1;
        out[(size_t)bl0 * MM + m]       = (x0 - mu0) * rsqrtf(var0 + 1e-3f) * gm + bt;
        out[(size_t)(bl0 + 1) * MM + m] = (x1 - mu1) * rsqrtf(var1 + 1e-3f) * gm + bt;
    }
}

extern "C" void kernel_launch(void* const* d_in, const int* in_sizes, int n_in,
                              void* d_out, int out_size) {
    const float* q     = (const float*)d_in[0];
    const float* k     = (const float*)d_in[1];
    const float* vq    = (const float*)d_in[2];
    const float* vk    = (const float*)d_in[3];
    const float* vexp  = (const float*)d_in[4];
    const float* scale = (const float*)d_in[5];
    const float* gamma = (const float*)d_in[6];
    const float* beta  = (const float*)d_in[7];
    float* out = (float*)d_out;

    int smem1 = (128 * KB_STRIDE + 64 * QT_STRIDE + 64) * (int)sizeof(float);
    cudaFuncSetAttribute(p1_kernel, cudaFuncAttributeMaxDynamicSharedMemorySize, smem1);
    p1_kernel<<<1280, 256, smem1>>>(q, k, vk, vexp, scale);

    int smem2 = (128 * ES + 128 * VS) * (int)sizeof(float);
    cudaFuncSetAttribute(k2_kernel, cudaFuncAttributeMaxDynamicSharedMemorySize, smem2);
    k2_kernel<<<256, 256, smem2>>>();

    k3_kernel<<<BB * LL / 2, 256>>>(q, vq, gamma, beta, out);
}

// round 12
// speedup vs baseline: 1.0276x; 1.0229x over previous
#include <cuda_runtime.h>

#define BB 8
#define LL 512
#define KK 512
#define MM 64
#define NN 64
#define PDIM 64
#define DD 64

// scratch (device globals; no allocations)
__device__ float g_sum4[BB * 4 * LL];         // 64 KB per-(b,ktile) partial row sums
__device__ float g_vkc [BB * KK * NN];        // 1 MB
__device__ float g_tmp4[BB * 4 * LL * NN];    // 4 MB  split-K partial tmp

#define KB_STRIDE 68
#define QT_STRIDE 68
#define ES_STRIDE 68

// ============ K1: vkc[b,k,n] = sum_p vk[b,k,p,n] * vexp[b,k,p] ============
// (measured 14.1us, DRAM 62%)
__global__ void __launch_bounds__(256) kv_kernel(
    const float* __restrict__ vk, const float* __restrict__ vexp) {
    __shared__ float sve[256];
    __shared__ __align__(16) float4 red[256];
    int t = threadIdx.x;
    int bk0 = blockIdx.x * 4;

    sve[t] = vexp[(size_t)bk0 * PDIM + t];
    __syncthreads();

    int slab = t >> 6;
    int tt = t & 63;
    int n4 = tt & 15;
    int pg = tt >> 4;
    const float4* vk4 = (const float4*)(vk + (size_t)(bk0 + slab) * PDIM * NN);
    const float* ve = &sve[slab * 64];
    float4 acc = make_float4(0.f, 0.f, 0.f, 0.f);
#pragma unroll
    for (int i = 0; i < 16; i++) {
        int p = pg * 16 + i;
        float4 a = vk4[p * 16 + n4];
        float e = ve[p];
        acc.x += a.x * e; acc.y += a.y * e; acc.z += a.z * e; acc.w += a.w * e;
    }
    red[t] = acc;
    __syncthreads();
    if (tt < 16) {
        float4 r0 = red[slab * 64 + n4];
        float4 r1 = red[slab * 64 + 16 + n4];
        float4 r2 = red[slab * 64 + 32 + n4];
        float4 r3 = red[slab * 64 + 48 + n4];
        float4 o = make_float4(r0.x + r1.x + r2.x + r3.x, r0.y + r1.y + r2.y + r3.y,
                               r0.z + r1.z + r2.z + r3.z, r0.w + r1.w + r2.w + r3.w);
        *(float4*)&g_vkc[(size_t)(bk0 + slab) * NN + n4 * 4] = o;
    }
}

// ============ SF: fused scores(128k x 64l) + exp + (E @ vkc chunk), split-K ============
// smem 68.3KB -> 2-3 CTAs/SM. Es overlaps dead qT region. E never touches HBM.
//   bufK[128][68] (k tile -> vkc chunk) | region2: qT[64][68] then Es[128][68] | ssum[64]
#define OFF_R2  (128 * KB_STRIDE)
#define OFF_SS  (OFF_R2 + 128 * ES_STRIDE)
#define SMEM_SF (OFF_SS + 64)

__global__ void __launch_bounds__(256) sf_kernel(
    const float* __restrict__ q, const float* __restrict__ k,
    const float* __restrict__ scale_p) {
    extern __shared__ float s[];
    float* bufK = s;               // [128][KB_STRIDE]
    float* qT   = s + OFF_R2;      // [64][QT_STRIDE]  (phase 1)
    float* Es   = s + OFF_R2;      // [128][ES_STRIDE] (phase 2, overlaps qT)
    float* ssum = s + OFF_SS;      // [64]
    int t = threadIdx.x;
    int bid = blockIdx.x;
    int b  = bid >> 5;
    int r  = bid & 31;
    int l0 = (r >> 2) * 64;
    int kt = r & 3;
    int k0 = kt * 128;

    // load k tile [128][64] coalesced
#pragma unroll
    for (int j = 0; j < 8; j++) {
        int v = t + j * 256;
        int row = v >> 4, c4 = v & 15;
        float4 x = *(const float4*)&k[((size_t)(b * KK + k0 + row)) * DD + c4 * 4];
        *(float4*)&bufK[row * KB_STRIDE + c4 * 4] = x;
    }
    // transpose q tile 64x64 -> qT[d][l]
#pragma unroll
    for (int i = 0; i < 4; i++) {
        int l = (t >> 4) + 16 * i;
        int d4 = t & 15;
        float4 x = *(const float4*)&q[((size_t)(b * LL + l0 + l)) * DD + d4 * 4];
        qT[(d4 * 4 + 0) * QT_STRIDE + l] = x.x;
        qT[(d4 * 4 + 1) * QT_STRIDE + l] = x.y;
        qT[(d4 * 4 + 2) * QT_STRIDE + l] = x.z;
        qT[(d4 * 4 + 3) * QT_STRIDE + l] = x.w;
    }
    if (t < 64) ssum[t] = 0.f;
    __syncthreads();

    // ---- GEMM1: scores. 4k x 8l per thread (proven r3 shape, ~80 regs) ----
    int tkg = t >> 3;          // k rows tkg*4..+3
    int tlg = t & 7;           // l groups (tlg*4 and 32+tlg*4)
    float acc[4][8];
#pragma unroll
    for (int a = 0; a < 4; a++)
#pragma unroll
        for (int c = 0; c < 8; c++) acc[a][c] = 0.f;

#pragma unroll 2
    for (int d0 = 0; d0 < DD; d0 += 4) {
        float4 kv4[4];
#pragma unroll
        for (int ki = 0; ki < 4; ki++)
            kv4[ki] = *(float4*)&bufK[(tkg * 4 + ki) * KB_STRIDE + d0];
#pragma unroll
        for (int dd = 0; dd < 4; dd++) {
            float4 qa = *(float4*)&qT[(d0 + dd) * QT_STRIDE + tlg * 4];
            float4 qb = *(float4*)&qT[(d0 + dd) * QT_STRIDE + 32 + tlg * 4];
            float kd[4];
            kd[0] = ((float*)&kv4[0])[dd];
            kd[1] = ((float*)&kv4[1])[dd];
            kd[2] = ((float*)&kv4[2])[dd];
            kd[3] = ((float*)&kv4[3])[dd];
#pragma unroll
            for (int ki = 0; ki < 4; ki++) {
                acc[ki][0] += kd[ki] * qa.x;
                acc[ki][1] += kd[ki] * qa.y;
                acc[ki][2] += kd[ki] * qa.z;
                acc[ki][3] += kd[ki] * qa.w;
                acc[ki][4] += kd[ki] * qb.x;
                acc[ki][5] += kd[ki] * qb.y;
                acc[ki][6] += kd[ki] * qb.z;
                acc[ki][7] += kd[ki] * qb.w;
            }
        }
    }
    __syncthreads();   // GEMM1 reads of bufK/qT complete; regions become vkc/Es

    // ---- exp -> Es (smem only), row-sum partials; vkc chunk -> bufK ----
    float scale = *scale_p;
    float sacc[8];
#pragma unroll
    for (int j = 0; j < 8; j++) sacc[j] = 0.f;
#pragma unroll
    for (int ki = 0; ki < 4; ki++) {
        float4 e0, e1;
        e0.x = __expf(acc[ki][0] * scale);
        e0.y = __expf(acc[ki][1] * scale);
        e0.z = __expf(acc[ki][2] * scale);
        e0.w = __expf(acc[ki][3] * scale);
        e1.x = __expf(acc[ki][4] * scale);
        e1.y = __expf(acc[ki][5] * scale);
        e1.z = __expf(acc[ki][6] * scale);
        e1.w = __expf(acc[ki][7] * scale);
        sacc[0] += e0.x; sacc[1] += e0.y; sacc[2] += e0.z; sacc[3] += e0.w;
        sacc[4] += e1.x; sacc[5] += e1.y; sacc[6] += e1.z; sacc[7] += e1.w;
        *(float4*)&Es[(tkg * 4 + ki) * ES_STRIDE + tlg * 4]      = e0;
        *(float4*)&Es[(tkg * 4 + ki) * ES_STRIDE + 32 + tlg * 4] = e1;
    }
#pragma unroll
    for (int j = 0; j < 4; j++) atomicAdd(&ssum[tlg * 4 + j], sacc[j]);
#pragma unroll
    for (int j = 0; j < 4; j++) atomicAdd(&ssum[32 + tlg * 4 + j], sacc[4 + j]);
    // vkc chunk [128][64] into bufK
#pragma unroll
    for (int j = 0; j < 8; j++) {
        int v = t + j * 256;
        int row = v >> 4, c4 = v & 15;
        float4 x = *(const float4*)&g_vkc[((size_t)(b * KK + k0 + row)) * NN + c4 * 4];
        *(float4*)&bufK[row * KB_STRIDE + c4 * 4] = x;
    }
    __syncthreads();
    if (t < 64) g_sum4[((size_t)(b * 4 + kt)) * LL + l0 + t] = ssum[t];

    // ---- GEMM2: tmp_partial[l][n] = sum_k Es[k][l]*vkc[k][n]; 4l x 4n (proven k2 loop) ----
    int tn = t >> 4, tl = t & 15;
    float acc2[4][4];
#pragma unroll
    for (int a = 0; a < 4; a++)
#pragma unroll
        for (int c = 0; c < 4; c++) acc2[a][c] = 0.f;
#pragma unroll 4
    for (int kk = 0; kk < 128; kk++) {
        float4 e4 = *(float4*)&Es[kk * ES_STRIDE + tl * 4];
        float4 v4 = *(float4*)&bufK[kk * KB_STRIDE + tn * 4];
        float ee[4] = {e4.x, e4.y, e4.z, e4.w};
        float vv[4] = {v4.x, v4.y, v4.z, v4.w};
#pragma unroll
        for (int li = 0; li < 4; li++)
#pragma unroll
            for (int nj = 0; nj < 4; nj++)
                acc2[li][nj] += ee[li] * vv[nj];
    }
#pragma unroll
    for (int li = 0; li < 4; li++) {
        int l = l0 + tl * 4 + li;
        float4 o = {acc2[li][0], acc2[li][1], acc2[li][2], acc2[li][3]};
        *(float4*)&g_tmp4[(((size_t)(b * 4 + kt)) * LL + l) * NN + tn * 4] = o;
    }
}

// ============ K3: attn = vq @ tmp (combined+normalized), residual + LN ============
// (measured 18.7us)
__global__ void __launch_bounds__(256) k3_kernel(
    const float* __restrict__ q, const float* __restrict__ vq,
    const float* __restrict__ gamma, const float* __restrict__ beta,
    float* __restrict__ out) {
    int bl = blockIdx.x;             // b*512 + l
    int b = bl >> 9, l = bl & 511;
    __shared__ __align__(16) float stmp[64];
    __shared__ float sq[64];
    __shared__ float so[64];
    __shared__ float rs[8], rq[8];
    int t = threadIdx.x;
    if (t < 64) {
        float ssum = 0.f;
        float v = 0.f;
#pragma unroll
        for (int i = 0; i < 4; i++) {
            ssum += g_sum4[((size_t)(b * 4 + i)) * LL + l];
            v    += g_tmp4[(((size_t)(b * 4 + i)) * LL + l) * NN + t];
        }
        stmp[t] = v / ssum;
        sq[t]   = q[(size_t)bl * DD + t];
    }
    __syncthreads();

    int n4 = t & 15;
    float4 tm = ((float4*)stmp)[n4];
    const float4* vq4 = (const float4*)(vq + (size_t)bl * MM * NN);
    float p[4];
#pragma unroll
    for (int i = 0; i < 4; i++) {
        float4 v = vq4[t + i * 256];         // m = (t>>4) + 16*i, n-chunk = n4
        p[i] = v.x * tm.x + v.y * tm.y + v.z * tm.z + v.w * tm.w;
    }
#pragma unroll
    for (int o = 8; o; o >>= 1)
#pragma unroll
        for (int i = 0; i < 4; i++)
            p[i] += __shfl_down_sync(0xFFFFFFFFu, p[i], o, 16);
    if ((t & 15) == 0) {
        int g = t >> 4;
#pragma unroll
        for (int i = 0; i < 4; i++) so[g + 16 * i] = p[i];
    }
    __syncthreads();

    int m = t & 63;
    float x = sq[m] + so[m];                 // residual (M == D)
    float s1 = x, s2 = x * x;
#pragma unroll
    for (int o = 16; o; o >>= 1) {
        s1 += __shfl_xor_sync(0xFFFFFFFFu, s1, o);
        s2 += __shfl_xor_sync(0xFFFFFFFFu, s2, o);
    }
    int lane = t & 31, w = t >> 5;
    if (lane == 0) { rs[w] = s1; rq[w] = s2; }
    __syncthreads();
    float a = 0.f, b2 = 0.f;
#pragma unroll
    for (int i = 0; i < 8; i++) { a += rs[i]; b2 += rq[i]; }
    float mu   = a * (1.f / 256.f);          // each m replicated 4x -> exact mean
    float var  = b2 * (1.f / 256.f) - mu * mu;
    float rstd = rsqrtf(var + 1e-3f);
    if (t < 64)
        out[(size_t)bl * MM + m] = (x - mu) * rstd * gamma[m] + beta[m];
}

extern "C" void kernel_launch(void* const* d_in, const int* in_sizes, int n_in,
                              void* d_out, int out_size) {
    const float* q     = (const float*)d_in[0];
    const float* k     = (const float*)d_in[1];
    const float* vq    = (const float*)d_in[2];
    const float* vk    = (const float*)d_in[3];
    const float* vexp  = (const float*)d_in[4];
    const float* scale = (const float*)d_in[5];
    const float* gamma = (const float*)d_in[6];
    const float* beta  = (const float*)d_in[7];
    float* out = (float*)d_out;

    kv_kernel<<<BB * KK / 4, 256>>>(vk, vexp);

    int smemS = SMEM_SF * (int)sizeof(float);
    cudaFuncSetAttribute(sf_kernel, cudaFuncAttributeMaxDynamicSharedMemorySize, smemS);
    sf_kernel<<<256, 256, smemS>>>(q, k, scale);

    k3_kernel<<<BB * LL, 256>>>(q, vq, gamma, beta, out);
}